// round 8
// baseline (speedup 1.0000x reference)
#include <cuda_runtime.h>

// Problem constants
#define SQ   256   // query length S
#define MLEN 256   // memory length M
#define BB   8     // batch
#define DD   512   // model dim
#define HH   8     // heads
#define HD   64    // head dim
#define KL   512   // key length = S + M

// Scratch (device globals; allocation-free)
__device__ float g_Q [BB*HH*SQ*HD];   // (b,h,s,hd)
__device__ float g_K [BB*HH*KL*HD];   // (b,h,k,hd)
__device__ float g_V [BB*HH*KL*HD];   // (b,h,k,hd)
__device__ float g_R [HH*KL*HD];      // (h,j,hd)
__device__ float g_Y [SQ*BB*DD];      // attn out (s,b,d)

// ---------------------------------------------------------------------------
// tf32 helpers
// ---------------------------------------------------------------------------
__device__ __forceinline__ unsigned f2tf(float f) {
    unsigned u;
    asm("cvt.rna.tf32.f32 %0, %1;" : "=r"(u) : "f"(f));
    return u;
}

__device__ __forceinline__ void mma8(float* c, const unsigned* a, const unsigned* b) {
    asm("mma.sync.aligned.m16n8k8.row.col.f32.tf32.tf32.f32 "
        "{%0,%1,%2,%3}, {%4,%5,%6,%7}, {%8,%9}, {%0,%1,%2,%3};"
        : "+f"(c[0]), "+f"(c[1]), "+f"(c[2]), "+f"(c[3])
        : "r"(a[0]), "r"(a[1]), "r"(a[2]), "r"(a[3]), "r"(b[0]), "r"(b[1]));
}

__device__ __forceinline__ float4 ldg4(const float* p) {
    return *reinterpret_cast<const float4*>(p);
}

__device__ __forceinline__ uint4 cvt4(float4 v) {
    uint4 u;
    u.x = f2tf(v.x); u.y = f2tf(v.y); u.z = f2tf(v.z); u.w = f2tf(v.w);
    return u;
}

// ===========================================================================
// Projection GEMM: C = A (rows x 512) @ W^T
// BM=128, BN=128, BK=16, 256 threads, 8 warps (4m x 2n), warp tile 32x64.
// MODE 0: Q, 1: K, 2: V, 3: R, 4: out
// ===========================================================================
struct ProjSmem {
    unsigned As[128][20];
    unsigned Bs[128][20];
};

template<int MODE>
__device__ __forceinline__
void proj_body(ProjSmem& sm, int bx, int by,
               const float* __restrict__ A0, const float* __restrict__ A1,
               const float* __restrict__ W, float* __restrict__ Cext)
{
    const int row0 = by * 128;
    const int col0 = bx * 128;
    const int tid  = threadIdx.x;
    const int lr   = tid >> 2;        // 0..63
    const int lc   = (tid & 3) * 4;   // 0,4,8,12
    const int warp = tid >> 5;
    const int lane = tid & 31;
    const int g    = lane >> 2;       // 0..7
    const int t    = lane & 3;        // 0..3
    const int wm   = (warp & 3) * 32;
    const int wn   = (warp >> 2) * 64;

    auto aRow = [&](int r) -> const float* {
        if constexpr (MODE == 1 || MODE == 2)
            return (r < MLEN * BB) ? A0 + (size_t)r * DD
                                   : A1 + (size_t)(r - MLEN * BB) * DD;
        else if constexpr (MODE == 4)
            return g_Y + (size_t)r * DD;
        else
            return A0 + (size_t)r * DD;
    };

    float acc[2][8][4];
    #pragma unroll
    for (int i = 0; i < 2; i++)
        #pragma unroll
        for (int j = 0; j < 8; j++)
            #pragma unroll
            for (int l = 0; l < 4; l++) acc[i][j][l] = 0.f;

    float4 rA0 = ldg4(aRow(row0 + lr)      + lc);
    float4 rA1 = ldg4(aRow(row0 + lr + 64) + lc);
    float4 rB0 = ldg4(W + (size_t)(col0 + lr) * DD + lc);
    float4 rB1 = ldg4(W + (size_t)(col0 + lr + 64) * DD + lc);

    for (int k0 = 0; k0 < DD; k0 += 16) {
        *reinterpret_cast<uint4*>(&sm.As[lr][lc])      = cvt4(rA0);
        *reinterpret_cast<uint4*>(&sm.As[lr + 64][lc]) = cvt4(rA1);
        *reinterpret_cast<uint4*>(&sm.Bs[lr][lc])      = cvt4(rB0);
        *reinterpret_cast<uint4*>(&sm.Bs[lr + 64][lc]) = cvt4(rB1);
        __syncthreads();

        if (k0 + 16 < DD) {
            rA0 = ldg4(aRow(row0 + lr)      + k0 + 16 + lc);
            rA1 = ldg4(aRow(row0 + lr + 64) + k0 + 16 + lc);
            rB0 = ldg4(W + (size_t)(col0 + lr) * DD + k0 + 16 + lc);
            rB1 = ldg4(W + (size_t)(col0 + lr + 64) * DD + k0 + 16 + lc);
        }

        #pragma unroll
        for (int ks = 0; ks < 16; ks += 8) {
            unsigned af[2][4], bf[8][2];
            #pragma unroll
            for (int mt = 0; mt < 2; mt++) {
                const int m = wm + mt * 16;
                af[mt][0] = sm.As[m + g][ks + t];
                af[mt][1] = sm.As[m + g + 8][ks + t];
                af[mt][2] = sm.As[m + g][ks + t + 4];
                af[mt][3] = sm.As[m + g + 8][ks + t + 4];
            }
            #pragma unroll
            for (int nt = 0; nt < 8; nt++) {
                const int n = wn + nt * 8 + g;
                bf[nt][0] = sm.Bs[n][ks + t];
                bf[nt][1] = sm.Bs[n][ks + t + 4];
            }
            #pragma unroll
            for (int mt = 0; mt < 2; mt++)
                #pragma unroll
                for (int nt = 0; nt < 8; nt++)
                    mma8(acc[mt][nt], af[mt], bf[nt]);
        }
        __syncthreads();
    }

    #pragma unroll
    for (int mt = 0; mt < 2; mt++) {
        #pragma unroll
        for (int nt = 0; nt < 8; nt++) {
            const int nc = col0 + wn + nt * 8 + 2 * t;
            const int h  = nc >> 6;
            const int hd = nc & 63;
            #pragma unroll
            for (int half = 0; half < 2; half++) {
                const int m = row0 + wm + mt * 16 + g + half * 8;
                float2 v = make_float2(acc[mt][nt][half * 2], acc[mt][nt][half * 2 + 1]);
                if constexpr (MODE == 0) {
                    const int s = m >> 3, b = m & 7;
                    *reinterpret_cast<float2*>(
                        g_Q + (((size_t)(b * HH + h)) * SQ + s) * HD + hd) = v;
                } else if constexpr (MODE == 1) {
                    const int j = m >> 3, b = m & 7;
                    *reinterpret_cast<float2*>(
                        g_K + (((size_t)(b * HH + h)) * KL + j) * HD + hd) = v;
                } else if constexpr (MODE == 2) {
                    const int j = m >> 3, b = m & 7;
                    *reinterpret_cast<float2*>(
                        g_V + (((size_t)(b * HH + h)) * KL + j) * HD + hd) = v;
                } else if constexpr (MODE == 3) {
                    *reinterpret_cast<float2*>(
                        g_R + ((size_t)h * KL + m) * HD + hd) = v;
                } else {
                    *reinterpret_cast<float2*>(Cext + (size_t)m * DD + nc) = v;
                }
            }
        }
    }
}

// Fused Q/K/V/R projections: 336 blocks total (BN=128 -> 4 n-blocks).
// [0,64) Q (16m x 4n); [64,192) K (32m x 4n); [192,320) V; [320,336) R (4m x 4n).
__global__ __launch_bounds__(256)
void proj_all(const float* __restrict__ x, const float* __restrict__ mem,
              const float* __restrict__ rel,
              const float* __restrict__ Wq, const float* __restrict__ Wk,
              const float* __restrict__ Wv, const float* __restrict__ Wr)
{
    __shared__ ProjSmem sm;
    const int id = blockIdx.x;
    if (id < 64) {
        proj_body<0>(sm, id & 3, id >> 2, x, nullptr, Wq, nullptr);
    } else if (id < 192) {
        const int l = id - 64;
        proj_body<1>(sm, l & 3, l >> 2, mem, x, Wk, nullptr);
    } else if (id < 320) {
        const int l = id - 192;
        proj_body<2>(sm, l & 3, l >> 2, mem, x, Wv, nullptr);
    } else {
        const int l = id - 320;
        proj_body<3>(sm, l & 3, l >> 2, rel, nullptr, Wr, nullptr);
    }
}

__global__ __launch_bounds__(256)
void proj_out(const float* __restrict__ Wo, float* __restrict__ out)
{
    __shared__ ProjSmem sm;
    proj_body<4>(sm, blockIdx.x, blockIdx.y, nullptr, nullptr, Wo, out);
}

// ===========================================================================
// Fused attention core (unchanged from R7): scores + softmax + PV.
// Grid (4, 64): x = 64-row query tile, y = bh. 256 threads, 8 warps (4x2).
// ===========================================================================
#define SST 516   // S row stride (floats)
#define ATTN_SMEM (64*516 + 64*68 + 64 + 64 + 64*72)

__global__ __launch_bounds__(256)
void attn_fused(const float* __restrict__ ub, const float* __restrict__ vb)
{
    extern __shared__ float dsm[];
    float*    S   = dsm;                    // 64*516
    float*    Qs  = dsm + 64 * 516;         // 64*68
    float*    us  = Qs + 64 * 68;           // 64
    float*    vsm = us + 64;                // 64
    unsigned* BV  = (unsigned*)(vsm + 64);  // 64*72

    const int q0 = blockIdx.x * 64;
    const int bh = blockIdx.y;
    const int b  = bh >> 3;
    const int h  = bh & 7;

    const int tid  = threadIdx.x;
    const int warp = tid >> 5;
    const int lane = tid & 31;
    const int g    = lane >> 2;      // 0..7
    const int t    = lane & 3;       // 0..3
    const int wm   = (warp & 3) * 16;
    const int wn   = (warp >> 2) * 32;

    const int ldr = tid >> 2;
    const int ldc = (tid & 3) * 16;

    // ---- Load Q tile + biases -------------------------------------------
    {
        const float* Qsrc = g_Q + ((size_t)bh * SQ + q0 + ldr) * HD;
        #pragma unroll
        for (int i = 0; i < 4; i++) {
            float4 v = ldg4(Qsrc + ldc + i * 4);
            *reinterpret_cast<float4*>(&Qs[ldr * 68 + ldc + i * 4]) = v;
        }
        if (tid < 64)       us[tid]        = ub[h * HD + tid];
        else if (tid < 128) vsm[tid - 64]  = vb[h * HD + tid - 128 + 64];
    }
    __syncthreads();

    // ---- Phase 1+2: score GEMMs into smem S -----------------------------
    #pragma unroll 1
    for (int ph = 0; ph < 2; ph++) {
        const float* bias = ph ? vsm : us;
        const float* Bsrc = ph ? (g_R + (size_t)h * KL * HD)
                               : (g_K + (size_t)bh * KL * HD);

        unsigned af[8][4];
        #pragma unroll
        for (int ks = 0; ks < 8; ks++) {
            const int c0 = ks * 8 + t;
            const int r0 = wm + g;
            af[ks][0] = f2tf(Qs[r0 * 68 + c0]            + bias[c0]);
            af[ks][1] = f2tf(Qs[(r0 + 8) * 68 + c0]      + bias[c0]);
            af[ks][2] = f2tf(Qs[r0 * 68 + c0 + 4]        + bias[c0 + 4]);
            af[ks][3] = f2tf(Qs[(r0 + 8) * 68 + c0 + 4]  + bias[c0 + 4]);
        }

        float4 rB[4];
        #pragma unroll
        for (int i = 0; i < 4; i++)
            rB[i] = ldg4(Bsrc + (size_t)ldr * HD + ldc + i * 4);

        #pragma unroll 1
        for (int nt0 = 0; nt0 < 8; nt0++) {
            #pragma unroll
            for (int i = 0; i < 4; i++)
                *reinterpret_cast<uint4*>(&BV[ldr * 68 + ldc + i * 4]) = cvt4(rB[i]);
            __syncthreads();

            if (nt0 < 7) {
                #pragma unroll
                for (int i = 0; i < 4; i++)
                    rB[i] = ldg4(Bsrc + (size_t)(nt0 * 64 + 64 + ldr) * HD + ldc + i * 4);
            }

            float acc[4][4];
            #pragma unroll
            for (int j = 0; j < 4; j++)
                #pragma unroll
                for (int l = 0; l < 4; l++) acc[j][l] = 0.f;

            #pragma unroll
            for (int ks = 0; ks < 8; ks++) {
                unsigned bf[4][2];
                #pragma unroll
                for (int nt = 0; nt < 4; nt++) {
                    const int n = wn + nt * 8 + g;
                    bf[nt][0] = BV[n * 68 + ks * 8 + t];
                    bf[nt][1] = BV[n * 68 + ks * 8 + t + 4];
                }
                #pragma unroll
                for (int nt = 0; nt < 4; nt++)
                    mma8(acc[nt], af[ks], bf[nt]);
            }

            const int n0 = nt0 * 64;
            if (ph == 0) {
                #pragma unroll
                for (int nt = 0; nt < 4; nt++) {
                    const int col = n0 + wn + nt * 8 + 2 * t;
                    #pragma unroll
                    for (int half = 0; half < 2; half++) {
                        const int q = wm + g + half * 8;
                        *reinterpret_cast<float2*>(&S[q * SST + col]) =
                            make_float2(acc[nt][half * 2] * 0.125f,
                                        acc[nt][half * 2 + 1] * 0.125f);
                    }
                }
            } else {
                #pragma unroll
                for (int nt = 0; nt < 4; nt++) {
                    const int j = n0 + wn + nt * 8 + 2 * t;
                    #pragma unroll
                    for (int half = 0; half < 2; half++) {
                        const int q  = wm + g + half * 8;
                        const int bk = q0 + q + MLEN - j;
                        if (bk >= 0)     S[q * SST + bk]     += 0.125f * acc[nt][half * 2];
                        if (bk - 1 >= 0) S[q * SST + bk - 1] += 0.125f * acc[nt][half * 2 + 1];
                    }
                }
            }
            __syncthreads();
        }
    }

    // ---- Phase 3: softmax in smem (8 warps x 8 rows) --------------------
    #pragma unroll 1
    for (int r = 0; r < 8; r++) {
        const int row  = warp * 8 + r;
        const int kmax = q0 + row + MLEN;
        float* Srow = S + row * SST;

        float vals[16];
        float mx = -1e30f;
        #pragma unroll
        for (int i = 0; i < 16; i++) {
            const int k = i * 32 + lane;
            float s = (k <= kmax) ? Srow[k] : -1e30f;
            vals[i] = s;
            mx = fmaxf(mx, s);
        }
        #pragma unroll
        for (int o = 16; o > 0; o >>= 1)
            mx = fmaxf(mx, __shfl_xor_sync(0xffffffffu, mx, o));

        float sum = 0.f;
        #pragma unroll
        for (int i = 0; i < 16; i++) {
            const float e = __expf(vals[i] - mx);
            vals[i] = e;
            sum += e;
        }
        #pragma unroll
        for (int o = 16; o > 0; o >>= 1)
            sum += __shfl_xor_sync(0xffffffffu, sum, o);

        const float inv = 1.f / sum;
        #pragma unroll
        for (int i = 0; i < 16; i++) {
            const int k = i * 32 + lane;
            Srow[k] = (k <= kmax) ? vals[i] * inv : 0.f;
        }
    }
    __syncthreads();

    // ---- Phase 4: PV ----------------------------------------------------
    {
        const float* Vsrc = g_V + (size_t)bh * KL * HD;

        float acc[4][4];
        #pragma unroll
        for (int j = 0; j < 4; j++)
            #pragma unroll
            for (int l = 0; l < 4; l++) acc[j][l] = 0.f;

        float4 rV[4];
        #pragma unroll
        for (int i = 0; i < 4; i++)
            rV[i] = ldg4(Vsrc + (size_t)ldr * HD + ldc + i * 4);

        #pragma unroll 1
        for (int kt = 0; kt < 8; kt++) {
            #pragma unroll
            for (int i = 0; i < 4; i++)
                *reinterpret_cast<uint4*>(&BV[ldr * 72 + ldc + i * 4]) = cvt4(rV[i]);
            __syncthreads();

            if (kt < 7) {
                #pragma unroll
                for (int i = 0; i < 4; i++)
                    rV[i] = ldg4(Vsrc + (size_t)(kt * 64 + 64 + ldr) * HD + ldc + i * 4);
            }

            #pragma unroll
            for (int ks = 0; ks < 8; ks++) {
                const int kk = kt * 64 + ks * 8;
                const int r0 = wm + g;
                unsigned af[4];
                af[0] = f2tf(S[r0 * SST + kk + t]);
                af[1] = f2tf(S[(r0 + 8) * SST + kk + t]);
                af[2] = f2tf(S[r0 * SST + kk + t + 4]);
                af[3] = f2tf(S[(r0 + 8) * SST + kk + t + 4]);

                unsigned bf[4][2];
                #pragma unroll
                for (int nt = 0; nt < 4; nt++) {
                    const int n = wn + nt * 8 + g;
                    bf[nt][0] = BV[(ks * 8 + t) * 72 + n];
                    bf[nt][1] = BV[(ks * 8 + t + 4) * 72 + n];
                }
                #pragma unroll
                for (int nt = 0; nt < 4; nt++)
                    mma8(acc[nt], af, bf[nt]);
            }
            __syncthreads();
        }

        #pragma unroll
        for (int nt = 0; nt < 4; nt++) {
            const int hd = wn + nt * 8 + 2 * t;
            #pragma unroll
            for (int half = 0; half < 2; half++) {
                const int q = q0 + wm + g + half * 8;
                *reinterpret_cast<float2*>(
                    &g_Y[((size_t)q * BB + b) * DD + h * HD + hd]) =
                    make_float2(acc[nt][half * 2], acc[nt][half * 2 + 1]);
            }
        }
    }
}

// ---------------------------------------------------------------------------
extern "C" void kernel_launch(void* const* d_in, const int* in_sizes, int n_in,
                              void* d_out, int out_size)
{
    const float* x    = (const float*)d_in[0];
    const float* mem  = (const float*)d_in[1];
    const float* rel  = (const float*)d_in[2];
    // d_in[3] = attn_mask: pure causal, recomputed in-kernel; unused.
    const float* Wq   = (const float*)d_in[4];
    const float* Wk   = (const float*)d_in[5];
    const float* Wv   = (const float*)d_in[6];
    const float* Wr   = (const float*)d_in[7];
    const float* Wo   = (const float*)d_in[8];
    const float* ub   = (const float*)d_in[9];
    const float* vb   = (const float*)d_in[10];
    float* out = (float*)d_out;

    cudaFuncSetAttribute(attn_fused, cudaFuncAttributeMaxDynamicSharedMemorySize,
                         ATTN_SMEM * 4);

    // All projections in one launch (336 blocks, BM=128 x BN=128)
    proj_all<<<336, 256>>>(x, mem, rel, Wq, Wk, Wv, Wr);

    // Fused scores + softmax + PV (256 blocks, 168 KB smem each)
    attn_fused<<<dim3(4, 64), 256, ATTN_SMEM * 4>>>(ub, vb);

    // Output projection (64 blocks)
    proj_out<<<dim3(4, 16), 256>>>(Wo, out);
}

// round 12
// speedup vs baseline: 1.0950x; 1.0950x over previous
#include <cuda_runtime.h>

// Problem constants
#define SQ   256   // query length S
#define MLEN 256   // memory length M
#define BB   8     // batch
#define DD   512   // model dim
#define HH   8     // heads
#define HD   64    // head dim
#define KL   512   // key length = S + M

// Scratch (device globals; allocation-free)
__device__ float g_Q [BB*HH*SQ*HD];   // (b,h,s,hd)
__device__ float g_K [BB*HH*KL*HD];   // (b,h,k,hd)
__device__ float g_V [BB*HH*KL*HD];   // (b,h,k,hd)
__device__ float g_R [HH*KL*HD];      // (h,j,hd)
__device__ float g_Y [SQ*BB*DD];      // attn out (s,b,d)

// ---------------------------------------------------------------------------
// tf32 helpers
// ---------------------------------------------------------------------------
__device__ __forceinline__ unsigned f2tf(float f) {
    unsigned u;
    asm("cvt.rna.tf32.f32 %0, %1;" : "=r"(u) : "f"(f));
    return u;
}

__device__ __forceinline__ void mma8(float* c, const unsigned* a, const unsigned* b) {
    asm("mma.sync.aligned.m16n8k8.row.col.f32.tf32.tf32.f32 "
        "{%0,%1,%2,%3}, {%4,%5,%6,%7}, {%8,%9}, {%0,%1,%2,%3};"
        : "+f"(c[0]), "+f"(c[1]), "+f"(c[2]), "+f"(c[3])
        : "r"(a[0]), "r"(a[1]), "r"(a[2]), "r"(a[3]), "r"(b[0]), "r"(b[1]));
}

__device__ __forceinline__ float4 ldg4(const float* p) {
    return *reinterpret_cast<const float4*>(p);
}

__device__ __forceinline__ uint4 cvt4(float4 v) {
    uint4 u;
    u.x = f2tf(v.x); u.y = f2tf(v.y); u.z = f2tf(v.z); u.w = f2tf(v.w);
    return u;
}

// ===========================================================================
// Projection GEMM: C = A (rows x 512) @ W^T
// BM=128, BN=NT*16 (128 or 64), BK=16, 256 threads, 8 warps (4m x 2n),
// warp tile 32 x NT*8.
// MODE 0: Q, 1: K, 2: V, 3: R, 4: out
// ===========================================================================
struct ProjSmem {
    unsigned As[128][20];
    unsigned Bs[128][20];   // only first NT*16 rows used
};

template<int MODE, int NT>
__device__ __forceinline__
void proj_body(ProjSmem& sm, int bx, int by,
               const float* __restrict__ A0, const float* __restrict__ A1,
               const float* __restrict__ W, float* __restrict__ Cext)
{
    const int BN   = NT * 16;
    const int row0 = by * 128;
    const int col0 = bx * BN;
    const int tid  = threadIdx.x;
    const int lr   = tid >> 2;        // 0..63
    const int lc   = (tid & 3) * 4;   // 0,4,8,12
    const int warp = tid >> 5;
    const int lane = tid & 31;
    const int g    = lane >> 2;       // 0..7
    const int t    = lane & 3;        // 0..3
    const int wm   = (warp & 3) * 32;
    const int wn   = (warp >> 2) * (NT * 8);

    auto aRow = [&](int r) -> const float* {
        if constexpr (MODE == 1 || MODE == 2)
            return (r < MLEN * BB) ? A0 + (size_t)r * DD
                                   : A1 + (size_t)(r - MLEN * BB) * DD;
        else if constexpr (MODE == 4)
            return g_Y + (size_t)r * DD;
        else
            return A0 + (size_t)r * DD;
    };

    float acc[2][NT][4];
    #pragma unroll
    for (int i = 0; i < 2; i++)
        #pragma unroll
        for (int j = 0; j < NT; j++)
            #pragma unroll
            for (int l = 0; l < 4; l++) acc[i][j][l] = 0.f;

    float4 rA0 = ldg4(aRow(row0 + lr)      + lc);
    float4 rA1 = ldg4(aRow(row0 + lr + 64) + lc);
    float4 rB0 = ldg4(W + (size_t)(col0 + lr) * DD + lc);
    float4 rB1;
    if constexpr (NT == 8)
        rB1 = ldg4(W + (size_t)(col0 + lr + 64) * DD + lc);

    for (int k0 = 0; k0 < DD; k0 += 16) {
        *reinterpret_cast<uint4*>(&sm.As[lr][lc])      = cvt4(rA0);
        *reinterpret_cast<uint4*>(&sm.As[lr + 64][lc]) = cvt4(rA1);
        *reinterpret_cast<uint4*>(&sm.Bs[lr][lc])      = cvt4(rB0);
        if constexpr (NT == 8)
            *reinterpret_cast<uint4*>(&sm.Bs[lr + 64][lc]) = cvt4(rB1);
        __syncthreads();

        if (k0 + 16 < DD) {
            rA0 = ldg4(aRow(row0 + lr)      + k0 + 16 + lc);
            rA1 = ldg4(aRow(row0 + lr + 64) + k0 + 16 + lc);
            rB0 = ldg4(W + (size_t)(col0 + lr) * DD + k0 + 16 + lc);
            if constexpr (NT == 8)
                rB1 = ldg4(W + (size_t)(col0 + lr + 64) * DD + k0 + 16 + lc);
        }

        #pragma unroll
        for (int ks = 0; ks < 16; ks += 8) {
            unsigned af[2][4], bf[NT][2];
            #pragma unroll
            for (int mt = 0; mt < 2; mt++) {
                const int m = wm + mt * 16;
                af[mt][0] = sm.As[m + g][ks + t];
                af[mt][1] = sm.As[m + g + 8][ks + t];
                af[mt][2] = sm.As[m + g][ks + t + 4];
                af[mt][3] = sm.As[m + g + 8][ks + t + 4];
            }
            #pragma unroll
            for (int nt = 0; nt < NT; nt++) {
                const int n = wn + nt * 8 + g;
                bf[nt][0] = sm.Bs[n][ks + t];
                bf[nt][1] = sm.Bs[n][ks + t + 4];
            }
            #pragma unroll
            for (int mt = 0; mt < 2; mt++)
                #pragma unroll
                for (int nt = 0; nt < NT; nt++)
                    mma8(acc[mt][nt], af[mt], bf[nt]);
        }
        __syncthreads();
    }

    #pragma unroll
    for (int mt = 0; mt < 2; mt++) {
        #pragma unroll
        for (int nt = 0; nt < NT; nt++) {
            const int nc = col0 + wn + nt * 8 + 2 * t;
            const int h  = nc >> 6;
            const int hd = nc & 63;
            #pragma unroll
            for (int half = 0; half < 2; half++) {
                const int m = row0 + wm + mt * 16 + g + half * 8;
                float2 v = make_float2(acc[mt][nt][half * 2], acc[mt][nt][half * 2 + 1]);
                if constexpr (MODE == 0) {
                    const int s = m >> 3, b = m & 7;
                    *reinterpret_cast<float2*>(
                        g_Q + (((size_t)(b * HH + h)) * SQ + s) * HD + hd) = v;
                } else if constexpr (MODE == 1) {
                    const int j = m >> 3, b = m & 7;
                    *reinterpret_cast<float2*>(
                        g_K + (((size_t)(b * HH + h)) * KL + j) * HD + hd) = v;
                } else if constexpr (MODE == 2) {
                    const int j = m >> 3, b = m & 7;
                    *reinterpret_cast<float2*>(
                        g_V + (((size_t)(b * HH + h)) * KL + j) * HD + hd) = v;
                } else if constexpr (MODE == 3) {
                    *reinterpret_cast<float2*>(
                        g_R + ((size_t)h * KL + m) * HD + hd) = v;
                } else {
                    *reinterpret_cast<float2*>(Cext + (size_t)m * DD + nc) = v;
                }
            }
        }
    }
}

// Fused Q/K/V/R projections: 336 blocks (BN=128).
// [0,64) Q (16m x 4n); [64,192) K (32m x 4n); [192,320) V; [320,336) R (4m x 4n).
__global__ __launch_bounds__(256)
void proj_all(const float* __restrict__ x, const float* __restrict__ mem,
              const float* __restrict__ rel,
              const float* __restrict__ Wq, const float* __restrict__ Wk,
              const float* __restrict__ Wv, const float* __restrict__ Wr)
{
    __shared__ ProjSmem sm;
    const int id = blockIdx.x;
    if (id < 64) {
        proj_body<0, 8>(sm, id & 3, id >> 2, x, nullptr, Wq, nullptr);
    } else if (id < 192) {
        const int l = id - 64;
        proj_body<1, 8>(sm, l & 3, l >> 2, mem, x, Wk, nullptr);
    } else if (id < 320) {
        const int l = id - 192;
        proj_body<2, 8>(sm, l & 3, l >> 2, mem, x, Wv, nullptr);
    } else {
        const int l = id - 320;
        proj_body<3, 8>(sm, l & 3, l >> 2, rel, nullptr, Wr, nullptr);
    }
}

// Output projection: BN=64, grid (8,16) = 128 blocks for full-chip residency.
__global__ __launch_bounds__(256)
void proj_out(const float* __restrict__ Wo, float* __restrict__ out)
{
    __shared__ ProjSmem sm;
    proj_body<4, 4>(sm, blockIdx.x, blockIdx.y, nullptr, nullptr, Wo, out);
}

// ===========================================================================
// Fused attention core: scores (QK + shifted QR) + softmax + PV.
// Grid (4, 64): x = 64-row query tile, y = bh.
// 512 threads, 16 warps (4m x 4n), warp tile 16 x 16 (nt=2) per 64-wide pass.
// ===========================================================================
#define SST 516   // S row stride (floats)
#define ATTN_SMEM (64*516 + 64*68 + 64 + 64 + 64*72)

__global__ __launch_bounds__(512)
void attn_fused(const float* __restrict__ ub, const float* __restrict__ vb)
{
    extern __shared__ float dsm[];
    float*    S   = dsm;                    // 64*516
    float*    Qs  = dsm + 64 * 516;         // 64*68
    float*    us  = Qs + 64 * 68;           // 64
    float*    vsm = us + 64;                // 64
    unsigned* BV  = (unsigned*)(vsm + 64);  // 64*72

    const int q0 = blockIdx.x * 64;
    const int bh = blockIdx.y;
    const int b  = bh >> 3;
    const int h  = bh & 7;

    const int tid  = threadIdx.x;
    const int warp = tid >> 5;       // 0..15
    const int lane = tid & 31;
    const int g    = lane >> 2;      // 0..7
    const int t    = lane & 3;       // 0..3
    const int wm   = (warp & 3) * 16;   // 4 m-groups over 64 rows
    const int wn   = (warp >> 2) * 16;  // 4 n-groups over 64 cols

    // Tile loader: 512 threads cover 64x64: row tid>>3, cols (tid&7)*8 .. +7
    const int ldr = tid >> 3;        // 0..63
    const int ldc = (tid & 7) * 8;   // 0,8,...,56

    // ---- Load Q tile + biases -------------------------------------------
    {
        const float* Qsrc = g_Q + ((size_t)bh * SQ + q0 + ldr) * HD;
        #pragma unroll
        for (int i = 0; i < 2; i++) {
            float4 v = ldg4(Qsrc + ldc + i * 4);
            *reinterpret_cast<float4*>(&Qs[ldr * 68 + ldc + i * 4]) = v;
        }
        if (tid < 64)       us[tid]        = ub[h * HD + tid];
        else if (tid < 128) vsm[tid - 64]  = vb[h * HD + tid - 128 + 64];
    }
    __syncthreads();

    // ---- Phase 1+2: score GEMMs into smem S -----------------------------
    // PH 0: S[q][k]  = 0.125*(Q+u).K   (direct store)
    // PH 1: S[q][qg+256-j] += 0.125*(Q+v).R  (scatter-add)
    #pragma unroll 1
    for (int ph = 0; ph < 2; ph++) {
        const float* bias = ph ? vsm : us;
        const float* Bsrc = ph ? (g_R + (size_t)h * KL * HD)
                               : (g_K + (size_t)bh * KL * HD);

        // A fragments: (Q + bias) as tf32, 8 ksteps (per-warp, reg-resident)
        unsigned af[8][4];
        #pragma unroll
        for (int ks = 0; ks < 8; ks++) {
            const int c0 = ks * 8 + t;
            const int r0 = wm + g;
            af[ks][0] = f2tf(Qs[r0 * 68 + c0]            + bias[c0]);
            af[ks][1] = f2tf(Qs[(r0 + 8) * 68 + c0]      + bias[c0]);
            af[ks][2] = f2tf(Qs[r0 * 68 + c0 + 4]        + bias[c0 + 4]);
            af[ks][3] = f2tf(Qs[(r0 + 8) * 68 + c0 + 4]  + bias[c0 + 4]);
        }

        float4 rB[2];
        #pragma unroll
        for (int i = 0; i < 2; i++)
            rB[i] = ldg4(Bsrc + (size_t)ldr * HD + ldc + i * 4);

        #pragma unroll 1
        for (int nt0 = 0; nt0 < 8; nt0++) {
            #pragma unroll
            for (int i = 0; i < 2; i++)
                *reinterpret_cast<uint4*>(&BV[ldr * 68 + ldc + i * 4]) = cvt4(rB[i]);
            __syncthreads();

            if (nt0 < 7) {
                #pragma unroll
                for (int i = 0; i < 2; i++)
                    rB[i] = ldg4(Bsrc + (size_t)(nt0 * 64 + 64 + ldr) * HD + ldc + i * 4);
            }

            float acc[2][4];
            #pragma unroll
            for (int j = 0; j < 2; j++)
                #pragma unroll
                for (int l = 0; l < 4; l++) acc[j][l] = 0.f;

            #pragma unroll
            for (int ks = 0; ks < 8; ks++) {
                unsigned bf[2][2];
                #pragma unroll
                for (int nt = 0; nt < 2; nt++) {
                    const int n = wn + nt * 8 + g;
                    bf[nt][0] = BV[n * 68 + ks * 8 + t];
                    bf[nt][1] = BV[n * 68 + ks * 8 + t + 4];
                }
                #pragma unroll
                for (int nt = 0; nt < 2; nt++)
                    mma8(acc[nt], af[ks], bf[nt]);
            }

            const int n0 = nt0 * 64;
            if (ph == 0) {
                #pragma unroll
                for (int nt = 0; nt < 2; nt++) {
                    const int col = n0 + wn + nt * 8 + 2 * t;
                    #pragma unroll
                    for (int half = 0; half < 2; half++) {
                        const int q = wm + g + half * 8;
                        *reinterpret_cast<float2*>(&S[q * SST + col]) =
                            make_float2(acc[nt][half * 2] * 0.125f,
                                        acc[nt][half * 2 + 1] * 0.125f);
                    }
                }
            } else {
                #pragma unroll
                for (int nt = 0; nt < 2; nt++) {
                    const int j = n0 + wn + nt * 8 + 2 * t;
                    #pragma unroll
                    for (int half = 0; half < 2; half++) {
                        const int q  = wm + g + half * 8;
                        const int bk = q0 + q + MLEN - j;   // k for even j
                        if (bk >= 0)     S[q * SST + bk]     += 0.125f * acc[nt][half * 2];
                        if (bk - 1 >= 0) S[q * SST + bk - 1] += 0.125f * acc[nt][half * 2 + 1];
                    }
                }
            }
            __syncthreads();
        }
    }

    // ---- Phase 3: softmax in smem (16 warps x 4 rows) -------------------
    #pragma unroll 1
    for (int r = 0; r < 4; r++) {
        const int row  = warp * 4 + r;
        const int kmax = q0 + row + MLEN;
        float* Srow = S + row * SST;

        float vals[16];
        float mx = -1e30f;
        #pragma unroll
        for (int i = 0; i < 16; i++) {
            const int k = i * 32 + lane;
            float s = (k <= kmax) ? Srow[k] : -1e30f;
            vals[i] = s;
            mx = fmaxf(mx, s);
        }
        #pragma unroll
        for (int o = 16; o > 0; o >>= 1)
            mx = fmaxf(mx, __shfl_xor_sync(0xffffffffu, mx, o));

        float sum = 0.f;
        #pragma unroll
        for (int i = 0; i < 16; i++) {
            const float e = __expf(vals[i] - mx);
            vals[i] = e;
            sum += e;
        }
        #pragma unroll
        for (int o = 16; o > 0; o >>= 1)
            sum += __shfl_xor_sync(0xffffffffu, sum, o);

        const float inv = 1.f / sum;
        #pragma unroll
        for (int i = 0; i < 16; i++) {
            const int k = i * 32 + lane;
            Srow[k] = (k <= kmax) ? vals[i] * inv : 0.f;
        }
    }
    __syncthreads();

    // ---- Phase 4: PV (A = probs from smem, B = V tiles) -----------------
    {
        const float* Vsrc = g_V + (size_t)bh * KL * HD;

        float acc[2][4];
        #pragma unroll
        for (int j = 0; j < 2; j++)
            #pragma unroll
            for (int l = 0; l < 4; l++) acc[j][l] = 0.f;

        float4 rV[2];
        #pragma unroll
        for (int i = 0; i < 2; i++)
            rV[i] = ldg4(Vsrc + (size_t)ldr * HD + ldc + i * 4);

        #pragma unroll 1
        for (int kt = 0; kt < 8; kt++) {
            #pragma unroll
            for (int i = 0; i < 2; i++)
                *reinterpret_cast<uint4*>(&BV[ldr * 72 + ldc + i * 4]) = cvt4(rV[i]);
            __syncthreads();

            if (kt < 7) {
                #pragma unroll
                for (int i = 0; i < 2; i++)
                    rV[i] = ldg4(Vsrc + (size_t)(kt * 64 + 64 + ldr) * HD + ldc + i * 4);
            }

            #pragma unroll
            for (int ks = 0; ks < 8; ks++) {
                const int kk = kt * 64 + ks * 8;
                const int r0 = wm + g;
                unsigned af[4];
                af[0] = f2tf(S[r0 * SST + kk + t]);
                af[1] = f2tf(S[(r0 + 8) * SST + kk + t]);
                af[2] = f2tf(S[r0 * SST + kk + t + 4]);
                af[3] = f2tf(S[(r0 + 8) * SST + kk + t + 4]);

                unsigned bf[2][2];
                #pragma unroll
                for (int nt = 0; nt < 2; nt++) {
                    const int n = wn + nt * 8 + g;
                    bf[nt][0] = BV[(ks * 8 + t) * 72 + n];
                    bf[nt][1] = BV[(ks * 8 + t + 4) * 72 + n];
                }
                #pragma unroll
                for (int nt = 0; nt < 2; nt++)
                    mma8(acc[nt], af, bf[nt]);
            }
            __syncthreads();
        }

        #pragma unroll
        for (int nt = 0; nt < 2; nt++) {
            const int hd = wn + nt * 8 + 2 * t;
            #pragma unroll
            for (int half = 0; half < 2; half++) {
                const int q = q0 + wm + g + half * 8;
                *reinterpret_cast<float2*>(
                    &g_Y[((size_t)q * BB + b) * DD + h * HD + hd]) =
                    make_float2(acc[nt][half * 2], acc[nt][half * 2 + 1]);
            }
        }
    }
}

// ---------------------------------------------------------------------------
extern "C" void kernel_launch(void* const* d_in, const int* in_sizes, int n_in,
                              void* d_out, int out_size)
{
    const float* x    = (const float*)d_in[0];
    const float* mem  = (const float*)d_in[1];
    const float* rel  = (const float*)d_in[2];
    // d_in[3] = attn_mask: pure causal, recomputed in-kernel; unused.
    const float* Wq   = (const float*)d_in[4];
    const float* Wk   = (const float*)d_in[5];
    const float* Wv   = (const float*)d_in[6];
    const float* Wr   = (const float*)d_in[7];
    const float* Wo   = (const float*)d_in[8];
    const float* ub   = (const float*)d_in[9];
    const float* vb   = (const float*)d_in[10];
    float* out = (float*)d_out;

    cudaFuncSetAttribute(attn_fused, cudaFuncAttributeMaxDynamicSharedMemorySize,
                         ATTN_SMEM * 4);

    // All projections in one launch (336 blocks, 128x128 tiles)
    proj_all<<<336, 256>>>(x, mem, rel, Wq, Wk, Wv, Wr);

    // Fused scores + softmax + PV (256 blocks, 512 threads, 168 KB smem)
    attn_fused<<<dim3(4, 64), 512, ATTN_SMEM * 4>>>(ub, vb);

    // Output projection (128 blocks, 128x64 tiles)
    proj_out<<<dim3(8, 16), 256>>>(Wo, out);
}

// round 13
// speedup vs baseline: 1.1297x; 1.0316x over previous
#include <cuda_runtime.h>

// Problem constants
#define SQ   256   // query length S
#define MLEN 256   // memory length M
#define BB   8     // batch
#define DD   512   // model dim
#define HH   8     // heads
#define HD   64    // head dim
#define KL   512   // key length = S + M

// Scratch (device globals; allocation-free)
__device__ float g_Q [BB*HH*SQ*HD];   // (b,h,s,hd)
__device__ float g_K [BB*HH*KL*HD];   // (b,h,k,hd)
__device__ float g_V [BB*HH*KL*HD];   // (b,h,k,hd)
__device__ float g_R [HH*KL*HD];      // (h,j,hd)
__device__ float g_Y [SQ*BB*DD];      // attn out (s,b,d)

// ---------------------------------------------------------------------------
// tf32 helpers
// ---------------------------------------------------------------------------
__device__ __forceinline__ unsigned f2tf(float f) {
    unsigned u;
    asm("cvt.rna.tf32.f32 %0, %1;" : "=r"(u) : "f"(f));
    return u;
}

__device__ __forceinline__ void mma8(float* c, const unsigned* a, const unsigned* b) {
    asm("mma.sync.aligned.m16n8k8.row.col.f32.tf32.tf32.f32 "
        "{%0,%1,%2,%3}, {%4,%5,%6,%7}, {%8,%9}, {%0,%1,%2,%3};"
        : "+f"(c[0]), "+f"(c[1]), "+f"(c[2]), "+f"(c[3])
        : "r"(a[0]), "r"(a[1]), "r"(a[2]), "r"(a[3]), "r"(b[0]), "r"(b[1]));
}

__device__ __forceinline__ float4 ldg4(const float* p) {
    return *reinterpret_cast<const float4*>(p);
}

__device__ __forceinline__ uint4 cvt4(float4 v) {
    uint4 u;
    u.x = f2tf(v.x); u.y = f2tf(v.y); u.z = f2tf(v.z); u.w = f2tf(v.w);
    return u;
}

// ===========================================================================
// Projection GEMM (double-buffered): C = A (rows x 512) @ W^T
// BM=128, BN=NT*16 (128 or 64), BK=16, 256 threads, 8 warps (4m x 2n),
// warp tile 32 x NT*8. One __syncthreads per k-iter.
// MODE 0: Q, 1: K, 2: V, 3: R, 4: out
// ===========================================================================
struct ProjSmem {
    unsigned As[2][128][20];
    unsigned Bs[2][128][20];   // only first NT*16 rows used
};

template<int MODE, int NT>
__device__ __forceinline__
void proj_body(ProjSmem& sm, int bx, int by,
               const float* __restrict__ A0, const float* __restrict__ A1,
               const float* __restrict__ W, float* __restrict__ Cext)
{
    const int BN   = NT * 16;
    const int row0 = by * 128;
    const int col0 = bx * BN;
    const int tid  = threadIdx.x;
    const int lr   = tid >> 2;        // 0..63
    const int lc   = (tid & 3) * 4;   // 0,4,8,12
    const int warp = tid >> 5;
    const int lane = tid & 31;
    const int g    = lane >> 2;       // 0..7
    const int t    = lane & 3;        // 0..3
    const int wm   = (warp & 3) * 32;
    const int wn   = (warp >> 2) * (NT * 8);

    auto aRow = [&](int r) -> const float* {
        if constexpr (MODE == 1 || MODE == 2)
            return (r < MLEN * BB) ? A0 + (size_t)r * DD
                                   : A1 + (size_t)(r - MLEN * BB) * DD;
        else if constexpr (MODE == 4)
            return g_Y + (size_t)r * DD;
        else
            return A0 + (size_t)r * DD;
    };

    float acc[2][NT][4];
    #pragma unroll
    for (int i = 0; i < 2; i++)
        #pragma unroll
        for (int j = 0; j < NT; j++)
            #pragma unroll
            for (int l = 0; l < 4; l++) acc[i][j][l] = 0.f;

    // Prologue: tile 0 -> stage 0; tile 1 into regs.
    float4 rA0 = ldg4(aRow(row0 + lr)      + lc);
    float4 rA1 = ldg4(aRow(row0 + lr + 64) + lc);
    float4 rB0 = ldg4(W + (size_t)(col0 + lr) * DD + lc);
    float4 rB1;
    if constexpr (NT == 8)
        rB1 = ldg4(W + (size_t)(col0 + lr + 64) * DD + lc);

    *reinterpret_cast<uint4*>(&sm.As[0][lr][lc])      = cvt4(rA0);
    *reinterpret_cast<uint4*>(&sm.As[0][lr + 64][lc]) = cvt4(rA1);
    *reinterpret_cast<uint4*>(&sm.Bs[0][lr][lc])      = cvt4(rB0);
    if constexpr (NT == 8)
        *reinterpret_cast<uint4*>(&sm.Bs[0][lr + 64][lc]) = cvt4(rB1);

    rA0 = ldg4(aRow(row0 + lr)      + 16 + lc);
    rA1 = ldg4(aRow(row0 + lr + 64) + 16 + lc);
    rB0 = ldg4(W + (size_t)(col0 + lr) * DD + 16 + lc);
    if constexpr (NT == 8)
        rB1 = ldg4(W + (size_t)(col0 + lr + 64) * DD + 16 + lc);
    __syncthreads();

    for (int k0 = 0; k0 < DD; k0 += 16) {
        const int st = (k0 >> 4) & 1;

        #pragma unroll
        for (int ks = 0; ks < 16; ks += 8) {
            unsigned af[2][4], bf[NT][2];
            #pragma unroll
            for (int mt = 0; mt < 2; mt++) {
                const int m = wm + mt * 16;
                af[mt][0] = sm.As[st][m + g][ks + t];
                af[mt][1] = sm.As[st][m + g + 8][ks + t];
                af[mt][2] = sm.As[st][m + g][ks + t + 4];
                af[mt][3] = sm.As[st][m + g + 8][ks + t + 4];
            }
            #pragma unroll
            for (int nt = 0; nt < NT; nt++) {
                const int n = wn + nt * 8 + g;
                bf[nt][0] = sm.Bs[st][n][ks + t];
                bf[nt][1] = sm.Bs[st][n][ks + t + 4];
            }
            #pragma unroll
            for (int mt = 0; mt < 2; mt++)
                #pragma unroll
                for (int nt = 0; nt < NT; nt++)
                    mma8(acc[mt][nt], af[mt], bf[nt]);
        }

        if (k0 + 16 < DD) {
            // Stage in the prefetched tile, then start LDG for the one after.
            *reinterpret_cast<uint4*>(&sm.As[st ^ 1][lr][lc])      = cvt4(rA0);
            *reinterpret_cast<uint4*>(&sm.As[st ^ 1][lr + 64][lc]) = cvt4(rA1);
            *reinterpret_cast<uint4*>(&sm.Bs[st ^ 1][lr][lc])      = cvt4(rB0);
            if constexpr (NT == 8)
                *reinterpret_cast<uint4*>(&sm.Bs[st ^ 1][lr + 64][lc]) = cvt4(rB1);
            if (k0 + 32 < DD) {
                rA0 = ldg4(aRow(row0 + lr)      + k0 + 32 + lc);
                rA1 = ldg4(aRow(row0 + lr + 64) + k0 + 32 + lc);
                rB0 = ldg4(W + (size_t)(col0 + lr) * DD + k0 + 32 + lc);
                if constexpr (NT == 8)
                    rB1 = ldg4(W + (size_t)(col0 + lr + 64) * DD + k0 + 32 + lc);
            }
            __syncthreads();
        }
    }

    #pragma unroll
    for (int mt = 0; mt < 2; mt++) {
        #pragma unroll
        for (int nt = 0; nt < NT; nt++) {
            const int nc = col0 + wn + nt * 8 + 2 * t;
            const int h  = nc >> 6;
            const int hd = nc & 63;
            #pragma unroll
            for (int half = 0; half < 2; half++) {
                const int m = row0 + wm + mt * 16 + g + half * 8;
                float2 v = make_float2(acc[mt][nt][half * 2], acc[mt][nt][half * 2 + 1]);
                if constexpr (MODE == 0) {
                    const int s = m >> 3, b = m & 7;
                    *reinterpret_cast<float2*>(
                        g_Q + (((size_t)(b * HH + h)) * SQ + s) * HD + hd) = v;
                } else if constexpr (MODE == 1) {
                    const int j = m >> 3, b = m & 7;
                    *reinterpret_cast<float2*>(
                        g_K + (((size_t)(b * HH + h)) * KL + j) * HD + hd) = v;
                } else if constexpr (MODE == 2) {
                    const int j = m >> 3, b = m & 7;
                    *reinterpret_cast<float2*>(
                        g_V + (((size_t)(b * HH + h)) * KL + j) * HD + hd) = v;
                } else if constexpr (MODE == 3) {
                    *reinterpret_cast<float2*>(
                        g_R + ((size_t)h * KL + m) * HD + hd) = v;
                } else {
                    *reinterpret_cast<float2*>(Cext + (size_t)m * DD + nc) = v;
                }
            }
        }
    }
}

// Fused Q/K/V/R projections: 336 blocks (BN=128).
__global__ __launch_bounds__(256)
void proj_all(const float* __restrict__ x, const float* __restrict__ mem,
              const float* __restrict__ rel,
              const float* __restrict__ Wq, const float* __restrict__ Wk,
              const float* __restrict__ Wv, const float* __restrict__ Wr)
{
    __shared__ ProjSmem sm;
    const int id = blockIdx.x;
    if (id < 64) {
        proj_body<0, 8>(sm, id & 3, id >> 2, x, nullptr, Wq, nullptr);
    } else if (id < 192) {
        const int l = id - 64;
        proj_body<1, 8>(sm, l & 3, l >> 2, mem, x, Wk, nullptr);
    } else if (id < 320) {
        const int l = id - 192;
        proj_body<2, 8>(sm, l & 3, l >> 2, mem, x, Wv, nullptr);
    } else {
        const int l = id - 320;
        proj_body<3, 8>(sm, l & 3, l >> 2, rel, nullptr, Wr, nullptr);
    }
}

// Output projection: BN=64, grid (8,16) = 128 blocks for full-chip residency.
__global__ __launch_bounds__(256)
void proj_out(const float* __restrict__ Wo, float* __restrict__ out)
{
    __shared__ ProjSmem sm;
    proj_body<4, 4>(sm, blockIdx.x, blockIdx.y, nullptr, nullptr, Wo, out);
}

// ===========================================================================
// Fused attention core: scores (QK + shifted QR) + softmax + PV.
// Grid (4, 64): x = 64-row query tile, y = bh.
// 512 threads, 16 warps (4m x 4n). BV tile double-buffered: 1 sync per pass.
// ===========================================================================
#define SST 516   // S row stride (floats)
#define BVS (64*72)   // BV stage size (words)
#define ATTN_SMEM (64*516 + 64*68 + 64 + 64 + 2*BVS)

__global__ __launch_bounds__(512)
void attn_fused(const float* __restrict__ ub, const float* __restrict__ vb)
{
    extern __shared__ float dsm[];
    float*    S   = dsm;                    // 64*516
    float*    Qs  = dsm + 64 * 516;         // 64*68
    float*    us  = Qs + 64 * 68;           // 64
    float*    vsm = us + 64;                // 64
    unsigned* BV  = (unsigned*)(vsm + 64);  // 2 stages x 64*72

    const int q0 = blockIdx.x * 64;
    const int bh = blockIdx.y;
    const int b  = bh >> 3;
    const int h  = bh & 7;

    const int tid  = threadIdx.x;
    const int warp = tid >> 5;       // 0..15
    const int lane = tid & 31;
    const int g    = lane >> 2;      // 0..7
    const int t    = lane & 3;       // 0..3
    const int wm   = (warp & 3) * 16;   // 4 m-groups over 64 rows
    const int wn   = (warp >> 2) * 16;  // 4 n-groups over 64 cols

    // Tile loader: 512 threads cover 64x64: row tid>>3, cols (tid&7)*8 .. +7
    const int ldr = tid >> 3;        // 0..63
    const int ldc = (tid & 7) * 8;   // 0,8,...,56

    // ---- Load Q tile + biases -------------------------------------------
    {
        const float* Qsrc = g_Q + ((size_t)bh * SQ + q0 + ldr) * HD;
        #pragma unroll
        for (int i = 0; i < 2; i++) {
            float4 v = ldg4(Qsrc + ldc + i * 4);
            *reinterpret_cast<float4*>(&Qs[ldr * 68 + ldc + i * 4]) = v;
        }
        if (tid < 64)       us[tid]        = ub[h * HD + tid];
        else if (tid < 128) vsm[tid - 64]  = vb[h * HD + tid - 128 + 64];
    }
    __syncthreads();

    // ---- Phase 1+2: score GEMMs into smem S -----------------------------
    // PH 0: S[q][k]  = 0.125*(Q+u).K   (direct store)
    // PH 1: S[q][qg+256-j] += 0.125*(Q+v).R  (scatter-add)
    #pragma unroll 1
    for (int ph = 0; ph < 2; ph++) {
        const float* bias = ph ? vsm : us;
        const float* Bsrc = ph ? (g_R + (size_t)h * KL * HD)
                               : (g_K + (size_t)bh * KL * HD);

        // A fragments: (Q + bias) as tf32, 8 ksteps (per-warp, reg-resident)
        unsigned af[8][4];
        #pragma unroll
        for (int ks = 0; ks < 8; ks++) {
            const int c0 = ks * 8 + t;
            const int r0 = wm + g;
            af[ks][0] = f2tf(Qs[r0 * 68 + c0]            + bias[c0]);
            af[ks][1] = f2tf(Qs[(r0 + 8) * 68 + c0]      + bias[c0]);
            af[ks][2] = f2tf(Qs[r0 * 68 + c0 + 4]        + bias[c0 + 4]);
            af[ks][3] = f2tf(Qs[(r0 + 8) * 68 + c0 + 4]  + bias[c0 + 4]);
        }

        // Prologue: tile 0 -> stage 0; tile 1 into regs.
        float4 rB[2];
        #pragma unroll
        for (int i = 0; i < 2; i++)
            rB[i] = ldg4(Bsrc + (size_t)ldr * HD + ldc + i * 4);
        #pragma unroll
        for (int i = 0; i < 2; i++)
            *reinterpret_cast<uint4*>(&BV[ldr * 68 + ldc + i * 4]) = cvt4(rB[i]);
        #pragma unroll
        for (int i = 0; i < 2; i++)
            rB[i] = ldg4(Bsrc + (size_t)(64 + ldr) * HD + ldc + i * 4);
        __syncthreads();

        #pragma unroll 1
        for (int nt0 = 0; nt0 < 8; nt0++) {
            const int st = nt0 & 1;
            const unsigned* BVc = BV + st * BVS;

            if (nt0 < 7) {
                unsigned* BVn = BV + (st ^ 1) * BVS;
                #pragma unroll
                for (int i = 0; i < 2; i++)
                    *reinterpret_cast<uint4*>(&BVn[ldr * 68 + ldc + i * 4]) = cvt4(rB[i]);
                if (nt0 < 6) {
                    #pragma unroll
                    for (int i = 0; i < 2; i++)
                        rB[i] = ldg4(Bsrc + (size_t)(nt0 * 64 + 128 + ldr) * HD + ldc + i * 4);
                }
            }

            float acc[2][4];
            #pragma unroll
            for (int j = 0; j < 2; j++)
                #pragma unroll
                for (int l = 0; l < 4; l++) acc[j][l] = 0.f;

            #pragma unroll
            for (int ks = 0; ks < 8; ks++) {
                unsigned bf[2][2];
                #pragma unroll
                for (int nt = 0; nt < 2; nt++) {
                    const int n = wn + nt * 8 + g;
                    bf[nt][0] = BVc[n * 68 + ks * 8 + t];
                    bf[nt][1] = BVc[n * 68 + ks * 8 + t + 4];
                }
                #pragma unroll
                for (int nt = 0; nt < 2; nt++)
                    mma8(acc[nt], af[ks], bf[nt]);
            }

            const int n0 = nt0 * 64;
            if (ph == 0) {
                #pragma unroll
                for (int nt = 0; nt < 2; nt++) {
                    const int col = n0 + wn + nt * 8 + 2 * t;
                    #pragma unroll
                    for (int half = 0; half < 2; half++) {
                        const int q = wm + g + half * 8;
                        *reinterpret_cast<float2*>(&S[q * SST + col]) =
                            make_float2(acc[nt][half * 2] * 0.125f,
                                        acc[nt][half * 2 + 1] * 0.125f);
                    }
                }
            } else {
                #pragma unroll
                for (int nt = 0; nt < 2; nt++) {
                    const int j = n0 + wn + nt * 8 + 2 * t;
                    #pragma unroll
                    for (int half = 0; half < 2; half++) {
                        const int q  = wm + g + half * 8;
                        const int bk = q0 + q + MLEN - j;   // k for even j
                        if (bk >= 0)     S[q * SST + bk]     += 0.125f * acc[nt][half * 2];
                        if (bk - 1 >= 0) S[q * SST + bk - 1] += 0.125f * acc[nt][half * 2 + 1];
                    }
                }
            }
            __syncthreads();
        }
    }

    // ---- Phase 3: softmax in smem (16 warps x 4 rows) -------------------
    #pragma unroll 1
    for (int r = 0; r < 4; r++) {
        const int row  = warp * 4 + r;
        const int kmax = q0 + row + MLEN;
        float* Srow = S + row * SST;

        float vals[16];
        float mx = -1e30f;
        #pragma unroll
        for (int i = 0; i < 16; i++) {
            const int k = i * 32 + lane;
            float s = (k <= kmax) ? Srow[k] : -1e30f;
            vals[i] = s;
            mx = fmaxf(mx, s);
        }
        #pragma unroll
        for (int o = 16; o > 0; o >>= 1)
            mx = fmaxf(mx, __shfl_xor_sync(0xffffffffu, mx, o));

        float sum = 0.f;
        #pragma unroll
        for (int i = 0; i < 16; i++) {
            const float e = __expf(vals[i] - mx);
            vals[i] = e;
            sum += e;
        }
        #pragma unroll
        for (int o = 16; o > 0; o >>= 1)
            sum += __shfl_xor_sync(0xffffffffu, sum, o);

        const float inv = 1.f / sum;
        #pragma unroll
        for (int i = 0; i < 16; i++) {
            const int k = i * 32 + lane;
            Srow[k] = (k <= kmax) ? vals[i] * inv : 0.f;
        }
    }
    __syncthreads();

    // ---- Phase 4: PV (A = probs from smem, B = V tiles) -----------------
    {
        const float* Vsrc = g_V + (size_t)bh * KL * HD;

        float acc[2][4];
        #pragma unroll
        for (int j = 0; j < 2; j++)
            #pragma unroll
            for (int l = 0; l < 4; l++) acc[j][l] = 0.f;

        // Prologue: tile 0 -> stage 0; tile 1 into regs.
        float4 rV[2];
        #pragma unroll
        for (int i = 0; i < 2; i++)
            rV[i] = ldg4(Vsrc + (size_t)ldr * HD + ldc + i * 4);
        #pragma unroll
        for (int i = 0; i < 2; i++)
            *reinterpret_cast<uint4*>(&BV[ldr * 72 + ldc + i * 4]) = cvt4(rV[i]);
        #pragma unroll
        for (int i = 0; i < 2; i++)
            rV[i] = ldg4(Vsrc + (size_t)(64 + ldr) * HD + ldc + i * 4);
        __syncthreads();

        #pragma unroll 1
        for (int kt = 0; kt < 8; kt++) {
            const int st = kt & 1;
            const unsigned* BVc = BV + st * BVS;

            if (kt < 7) {
                unsigned* BVn = BV + (st ^ 1) * BVS;
                #pragma unroll
                for (int i = 0; i < 2; i++)
                    *reinterpret_cast<uint4*>(&BVn[ldr * 72 + ldc + i * 4]) = cvt4(rV[i]);
                if (kt < 6) {
                    #pragma unroll
                    for (int i = 0; i < 2; i++)
                        rV[i] = ldg4(Vsrc + (size_t)(kt * 64 + 128 + ldr) * HD + ldc + i * 4);
                }
            }

            #pragma unroll
            for (int ks = 0; ks < 8; ks++) {
                const int kk = kt * 64 + ks * 8;
                const int r0 = wm + g;
                unsigned af[4];
                af[0] = f2tf(S[r0 * SST + kk + t]);
                af[1] = f2tf(S[(r0 + 8) * SST + kk + t]);
                af[2] = f2tf(S[r0 * SST + kk + t + 4]);
                af[3] = f2tf(S[(r0 + 8) * SST + kk + t + 4]);

                unsigned bf[2][2];
                #pragma unroll
                for (int nt = 0; nt < 2; nt++) {
                    const int n = wn + nt * 8 + g;
                    bf[nt][0] = BVc[(ks * 8 + t) * 72 + n];
                    bf[nt][1] = BVc[(ks * 8 + t + 4) * 72 + n];
                }
                #pragma unroll
                for (int nt = 0; nt < 2; nt++)
                    mma8(acc[nt], af, bf[nt]);
            }
            __syncthreads();
        }

        #pragma unroll
        for (int nt = 0; nt < 2; nt++) {
            const int hd = wn + nt * 8 + 2 * t;
            #pragma unroll
            for (int half = 0; half < 2; half++) {
                const int q = q0 + wm + g + half * 8;
                *reinterpret_cast<float2*>(
                    &g_Y[((size_t)q * BB + b) * DD + h * HD + hd]) =
                    make_float2(acc[nt][half * 2], acc[nt][half * 2 + 1]);
            }
        }
    }
}

// ---------------------------------------------------------------------------
extern "C" void kernel_launch(void* const* d_in, const int* in_sizes, int n_in,
                              void* d_out, int out_size)
{
    const float* x    = (const float*)d_in[0];
    const float* mem  = (const float*)d_in[1];
    const float* rel  = (const float*)d_in[2];
    // d_in[3] = attn_mask: pure causal, recomputed in-kernel; unused.
    const float* Wq   = (const float*)d_in[4];
    const float* Wk   = (const float*)d_in[5];
    const float* Wv   = (const float*)d_in[6];
    const float* Wr   = (const float*)d_in[7];
    const float* Wo   = (const float*)d_in[8];
    const float* ub   = (const float*)d_in[9];
    const float* vb   = (const float*)d_in[10];
    float* out = (float*)d_out;

    cudaFuncSetAttribute(attn_fused, cudaFuncAttributeMaxDynamicSharedMemorySize,
                         ATTN_SMEM * 4);

    // All projections in one launch (336 blocks, 128x128 tiles, double-buffered)
    proj_all<<<336, 256>>>(x, mem, rel, Wq, Wk, Wv, Wr);

    // Fused scores + softmax + PV (256 blocks, 512 threads, ~187 KB smem)
    attn_fused<<<dim3(4, 64), 512, ATTN_SMEM * 4>>>(ub, vb);

    // Output projection (128 blocks, 128x64 tiles)
    proj_out<<<dim3(8, 16), 256>>>(Wo, out);
}